// round 9
// baseline (speedup 1.0000x reference)
#include <cuda_runtime.h>
#include <cuda_fp16.h>
#include <cstdint>

// Problem shape (fixed by the dataset)
constexpr int B = 8, C = 16, H = 512, W = 512;
constexpr int HW = H * W;            // 262144 = 2^18
constexpr int CHW = C * HW;
constexpr int NOUT = B * CHW;        // 33,554,432

// Splat: 1024 blocks x 256 pixels per batch (bids 0 .. 8191)
constexpr int SPLAT_BLK_PER_B = HW / 256;              // 1024
constexpr int N_SPLAT_BLKS    = B * SPLAT_BLK_PER_B;   // 8192
// Transpose: 512 blocks x 512 pixels per batch (bids 8192 .. 12287)
constexpr int TPOSE_BLK_PER_B = HW / 512;              // 512
constexpr int N_TPOSE_BLKS    = B * TPOSE_BLK_PER_B;   // 4096
constexpr int N_BLKS          = N_SPLAT_BLKS + N_TPOSE_BLKS;

// Channel-contiguous fp16 scratch accumulator, layout (B,H,W,C). 64 MiB.
// Zero at module load; the transpose role re-zeros every line it reads, so
// "scratch == 0 on entry" holds for every graph replay. No memset pass.
__device__ __half g_scratch[NOUT];

// Per-batch progress counters (self-reset at the end of each launch).
__device__ int g_cnt[B];    // splat blocks completed for batch b
__device__ int g_tcnt[B];   // transpose blocks completed for batch b

// ---------------------------------------------------------------------------
// 16-byte fp16 vector reduction (hard max RED width): 8 halves per request.
// ---------------------------------------------------------------------------
__device__ __forceinline__ void red_v4h2(__half2* p, __half2 a, __half2 b,
                                         __half2 c, __half2 d) {
    unsigned ra = *(unsigned*)&a, rb = *(unsigned*)&b;
    unsigned rc = *(unsigned*)&c, rd = *(unsigned*)&d;
    asm volatile("red.global.add.noftz.v4.f16x2 [%0], {%1, %2, %3, %4};"
                 :: "l"(p), "r"(ra), "r"(rb), "r"(rc), "r"(rd) : "memory");
}

__device__ __forceinline__ int ld_acquire(const int* p) {
    int v;
    asm volatile("ld.global.acquire.gpu.b32 %0, [%1];" : "=r"(v) : "l"(p) : "memory");
    return v;
}

// ---------------------------------------------------------------------------
// Fused pipeline kernel — NO shared memory, regs capped at 32, so the splat
// role keeps full occupancy (R5's fusion failed on smem+regs tax, not sync).
//   bid <  N_SPLAT_BLKS : splat 256 pixels (LSU-REDG-bound), signal batch.
//   bid >= N_SPLAT_BLKS : gate on batch counter, then transpose 512 pixels
//                         with direct coalesced scalar stores (DRAM-bound)
//                         and re-zero the scratch lines read.
// Splat blocks occupy low bids -> dispatched first -> gates always progress.
// ---------------------------------------------------------------------------
__global__ __launch_bounds__(256, 8)
void fused_kernel(const float* __restrict__ x,
                  const float2* __restrict__ grid,
                  float* __restrict__ out) {
    int bid = blockIdx.x;
    int t   = threadIdx.x;

    if (bid < N_SPLAT_BLKS) {
        // ------------------------------ SPLAT ------------------------------
        int b  = bid >> 10;                       // / 1024
        int hw = ((bid & 1023) << 8) + t;         // pixel in batch

        float2 g = __ldcs(grid + (size_t)b * HW + hw);

        float gi = fminf(fmaxf((g.x + 1.0f) * 0.5f * (float)H + 1.0f, 0.0f), (float)(H + 1));
        float gj = fminf(fmaxf((g.y + 1.0f) * 0.5f * (float)W + 1.0f, 0.0f), (float)(W + 1));

        int   fi  = (int)gi;                      // gi >= 0 so trunc == floor
        int   fj  = (int)gj;
        float fri = gi - (float)fi;
        float frj = gj - (float)fj;

        float w00 = (1.0f - fri) * (1.0f - frj);
        float w01 = (1.0f - fri) * frj;
        float w10 = fri * (1.0f - frj);
        float w11 = fri * frj;

        int oi0 = fi - 1;
        int oj0 = fj - 1;
        bool i0 = (unsigned)oi0       < (unsigned)H;
        bool i1 = (unsigned)(oi0 + 1) < (unsigned)H;
        bool j0 = (unsigned)oj0       < (unsigned)W;
        bool j1 = (unsigned)(oj0 + 1) < (unsigned)W;

        const float* xp = x + (size_t)b * CHW + hw;
        float v[C];
#pragma unroll
        for (int c = 0; c < C; c++) v[c] = __ldcs(xp + c * HW);

        __half2* o00 = (__half2*)(g_scratch + ((size_t)b * HW + (size_t)oi0 * W + oj0) * C);
        __half2* o10 = o00 + (size_t)W * 8;   // +16KB: different L2 slice

#define PACK4(dst, wgt, off)                                                    \
        {                                                                       \
            _Pragma("unroll")                                                   \
            for (int j = 0; j < 4; j++)                                         \
                dst[j] = __floats2half2_rn(v[2*((off)+j)] * (wgt),              \
                                           v[2*((off)+j)+1] * (wgt));           \
        }

        if (j0) {   // corners (i0,j0) and (i1,j0), slice-alternated
            __half2 a[4], c[4];
            if (i0) { PACK4(a, w00, 0); red_v4h2(o00,     a[0], a[1], a[2], a[3]); }
            if (i1) { PACK4(c, w10, 0); red_v4h2(o10,     c[0], c[1], c[2], c[3]); }
            if (i0) { PACK4(a, w00, 4); red_v4h2(o00 + 4, a[0], a[1], a[2], a[3]); }
            if (i1) { PACK4(c, w10, 4); red_v4h2(o10 + 4, c[0], c[1], c[2], c[3]); }
        }
        if (j1) {   // corners (i0,j1) and (i1,j1), slice-alternated
            __half2 a[4], c[4];
            if (i0) { PACK4(a, w01, 0); red_v4h2(o00 + 8,  a[0], a[1], a[2], a[3]); }
            if (i1) { PACK4(c, w11, 0); red_v4h2(o10 + 8,  c[0], c[1], c[2], c[3]); }
            if (i0) { PACK4(a, w01, 4); red_v4h2(o00 + 12, a[0], a[1], a[2], a[3]); }
            if (i1) { PACK4(c, w11, 4); red_v4h2(o10 + 12, c[0], c[1], c[2], c[3]); }
        }
#undef PACK4

        // Release: make this block's REDs globally visible, then count.
        __threadfence();
        __syncthreads();
        if (t == 0) atomicAdd(&g_cnt[b], 1);
    } else {
        // ---------------------------- TRANSPOSE ----------------------------
        int tb   = bid - N_SPLAT_BLKS;            // 0 .. 4095
        int b    = tb >> 9;                       // / 512
        int base = (tb & 511) * 512;              // pixel base within batch

        // Gate: wait for all 1024 splat blocks of this batch.
        if (t == 0) {
            while (ld_acquire(&g_cnt[b]) < SPLAT_BLK_PER_B) __nanosleep(64);
        }
        __syncthreads();

        const uint4 z = make_uint4(0u, 0u, 0u, 0u);

#pragma unroll
        for (int q = 0; q < 2; q++) {
            int p = base + t + 256 * q;           // pixel within batch
            uint4* sp = (uint4*)((__half2*)g_scratch + ((size_t)b * HW + p) * 8);
            uint4 a  = sp[0];                     // channels 0..7  (8 halves)
            uint4 bq = sp[1];                     // channels 8..15
            sp[0] = z;                            // re-zero for next replay
            sp[1] = z;

            float* ob = out + (size_t)b * CHW + p;   // lanes: consecutive p
#define ST2(word, c0)                                                           \
            {                                                                   \
                float2 f = __half22float2(*(__half2*)&(word));                  \
                __stcs(ob + (size_t)(c0)     * HW, f.x);                        \
                __stcs(ob + (size_t)(c0 + 1) * HW, f.y);                        \
            }
            ST2(a.x,  0)  ST2(a.y,  2)  ST2(a.z,  4)  ST2(a.w,  6)
            ST2(bq.x, 8)  ST2(bq.y, 10) ST2(bq.z, 12) ST2(bq.w, 14)
#undef ST2
        }

        // Self-reset counters for the next launch / graph replay.
        __syncthreads();
        if (t == 0) {
            __threadfence();
            int old = atomicAdd(&g_tcnt[b], 1);
            if (old == TPOSE_BLK_PER_B - 1) {     // last transpose block of b
                g_cnt[b] = 0;
                __threadfence();
                g_tcnt[b] = 0;
            }
        }
    }
}

extern "C" void kernel_launch(void* const* d_in, const int* in_sizes, int n_in,
                              void* d_out, int out_size) {
    const float*  x    = (const float*)d_in[0];
    const float2* grid = (const float2*)d_in[1];
    float*        out  = (float*)d_out;

    fused_kernel<<<N_BLKS, 256>>>(x, grid, out);
}

// round 10
// speedup vs baseline: 1.5470x; 1.5470x over previous
#include <cuda_runtime.h>
#include <cuda_fp16.h>
#include <cstdint>

// Problem shape (fixed by the dataset)
constexpr int B = 8, C = 16, H = 512, W = 512;
constexpr int HW = H * W;            // 262144 = 2^18
constexpr int CHW = C * HW;
constexpr int NPIX = B * HW;         // 2,097,152
constexpr int NOUT = B * CHW;        // 33,554,432

// Split-plane fp16 scratch, 64 MiB total:
//   plane LO = channels 0..7   : pixel p at bytes [p*16, p*16+16)
//   plane HI = channels 8..15  : same indexing, offset +32 MiB
// The two 16B REDs of one corner hit addresses 32MB apart -> different L2
// slices, eliminating the same-sector RMW turnaround that made the packed
// layout cost 6.35ns/RED vs the scalar baseline's 4.65ns/RED.
__device__ __half g_scratch[NOUT];
constexpr size_t HI_OFF_H2 = (size_t)NPIX * 4;   // half2 offset of HI plane

// ---------------------------------------------------------------------------
// 16-byte fp16 vector reduction (hard max RED width): 8 halves per request.
// ---------------------------------------------------------------------------
__device__ __forceinline__ void red_v4h2(__half2* p, __half2 a, __half2 b,
                                         __half2 c, __half2 d) {
    unsigned ra = *(unsigned*)&a, rb = *(unsigned*)&b;
    unsigned rc = *(unsigned*)&c, rd = *(unsigned*)&d;
    asm volatile("red.global.add.noftz.v4.f16x2 [%0], {%1, %2, %3, %4};"
                 :: "l"(p), "r"(ra), "r"(rb), "r"(rc), "r"(rd) : "memory");
}

// ---------------------------------------------------------------------------
// Inverse bilinear splat into split-plane scratch.
// 4 corners x 2 planes = 8 x 16B REDs per pixel; issue order alternates
// plane (32MB apart) and i-row (8KB apart) so consecutive REDs never share
// an L2 slice, and same-sector REDs (j-adjacent pixels) are >=4 apart.
// ---------------------------------------------------------------------------
__global__ __launch_bounds__(256)
void splat_kernel(const float* __restrict__ x,
                  const float2* __restrict__ grid) {
    int idx = blockIdx.x * 256 + threadIdx.x;

    int b  = idx >> 18;        // / HW
    int hw = idx & (HW - 1);   // % HW

    float2 g = __ldcs(grid + idx);   // single-use: evict-first

    float gi = fminf(fmaxf((g.x + 1.0f) * 0.5f * (float)H + 1.0f, 0.0f), (float)(H + 1));
    float gj = fminf(fmaxf((g.y + 1.0f) * 0.5f * (float)W + 1.0f, 0.0f), (float)(W + 1));

    int   fi  = (int)gi;            // gi >= 0 so trunc == floor
    int   fj  = (int)gj;
    float fri = gi - (float)fi;
    float frj = gj - (float)fj;

    float w00 = (1.0f - fri) * (1.0f - frj);
    float w01 = (1.0f - fri) * frj;
    float w10 = fri * (1.0f - frj);
    float w11 = fri * frj;

    int oi0 = fi - 1;
    int oj0 = fj - 1;
    bool i0 = (unsigned)oi0       < (unsigned)H;
    bool i1 = (unsigned)(oi0 + 1) < (unsigned)H;
    bool j0 = (unsigned)oj0       < (unsigned)W;
    bool j1 = (unsigned)oj0 + 1   < (unsigned)W;

    // 16 channel values, coalesced per channel, streaming (single use)
    const float* xp = x + (size_t)b * CHW + hw;
    float v[C];
#pragma unroll
    for (int c = 0; c < C; c++) v[c] = __ldcs(xp + c * HW);

    // Plane pointers for corner (oi0, oj0); pixel stride = 4 half2 (16B).
    size_t p00 = (size_t)b * HW + (size_t)oi0 * W + oj0;
    __half2* l00 = (__half2*)g_scratch + p00 * 4;          // LO, (i0,j0)
    __half2* l10 = l00 + (size_t)W * 4;                    // LO, (i1,j0): +8KB
    __half2* h00 = (__half2*)g_scratch + HI_OFF_H2 + p00 * 4;  // HI: +32MB
    __half2* h10 = h00 + (size_t)W * 4;

    // Pack 4 half2 (= channels [8*half .. 8*half+7]) scaled by wgt.
#define PACK4(dst, wgt, half)                                                   \
    {                                                                           \
        _Pragma("unroll")                                                       \
        for (int j = 0; j < 4; j++)                                             \
            dst[j] = __floats2half2_rn(v[8*(half) + 2*j]     * (wgt),           \
                                       v[8*(half) + 2*j + 1] * (wgt));          \
    }

    if (j0) {   // corners (i0,j0)/(i1,j0): plane- and i-alternated issue
        __half2 a[4], c[4];
        if (i0) { PACK4(a, w00, 0); red_v4h2(l00, a[0], a[1], a[2], a[3]); }
        if (i1) { PACK4(c, w10, 0); red_v4h2(l10, c[0], c[1], c[2], c[3]); }
        if (i0) { PACK4(a, w00, 1); red_v4h2(h00, a[0], a[1], a[2], a[3]); }
        if (i1) { PACK4(c, w10, 1); red_v4h2(h10, c[0], c[1], c[2], c[3]); }
    }
    if (j1) {   // corners (i0,j1)/(i1,j1): next pixel = +4 half2 (16B)
        __half2 a[4], c[4];
        if (i0) { PACK4(a, w01, 0); red_v4h2(l00 + 4, a[0], a[1], a[2], a[3]); }
        if (i1) { PACK4(c, w11, 0); red_v4h2(l10 + 4, c[0], c[1], c[2], c[3]); }
        if (i0) { PACK4(a, w01, 1); red_v4h2(h00 + 4, a[0], a[1], a[2], a[3]); }
        if (i1) { PACK4(c, w11, 1); red_v4h2(h10 + 4, c[0], c[1], c[2], c[3]); }
    }
#undef PACK4
}

// ---------------------------------------------------------------------------
// Transpose split-plane fp16 scratch -> f32 out (B,C,H,W).
// Block = 128 threads, tile = 512 consecutive pixels (R8 config, best known).
// Reads one uint4 from each plane per pixel (both perfectly coalesced).
// ---------------------------------------------------------------------------
__global__ __launch_bounds__(128)
void transpose_kernel(const __half2* __restrict__ s, float* __restrict__ out) {
    __shared__ __half2 sm[8][512];   // sm[r][p] = channels (2r, 2r+1) of pixel p

    int base = blockIdx.x * 512;
    int t = threadIdx.x;

#pragma unroll
    for (int q = 0; q < 4; q++) {
        int p = t + 128 * q;
        const uint4* lp = (const uint4*)(s + (size_t)(base + p) * 4);
        const uint4* hp = (const uint4*)(s + HI_OFF_H2 + (size_t)(base + p) * 4);
        uint4 a  = __ldcs(lp);       // channels 0..7
        uint4 bq = __ldcs(hp);       // channels 8..15
        sm[0][p] = *(__half2*)&a.x;  sm[1][p] = *(__half2*)&a.y;
        sm[2][p] = *(__half2*)&a.z;  sm[3][p] = *(__half2*)&a.w;
        sm[4][p] = *(__half2*)&bq.x; sm[5][p] = *(__half2*)&bq.y;
        sm[6][p] = *(__half2*)&bq.z; sm[7][p] = *(__half2*)&bq.w;
    }
    __syncthreads();

    int b  = base >> 18;
    int hw = base & (HW - 1);
    float* ob = out + (size_t)b * CHW + hw;

#pragma unroll
    for (int r = 0; r < 8; r++) {
        uint4 raw = *(const uint4*)&sm[r][4 * t];   // 4 half2 of channel pair r
        float2 f0 = __half22float2(*(__half2*)&raw.x);
        float2 f1 = __half22float2(*(__half2*)&raw.y);
        float2 f2 = __half22float2(*(__half2*)&raw.z);
        float2 f3 = __half22float2(*(__half2*)&raw.w);
        float4 ve = make_float4(f0.x, f1.x, f2.x, f3.x);  // channel 2r
        float4 vo = make_float4(f0.y, f1.y, f2.y, f3.y);  // channel 2r+1
        __stcs((float4*)(ob + (size_t)(2*r)     * HW) + t, ve);
        __stcs((float4*)(ob + (size_t)(2*r + 1) * HW) + t, vo);
    }
}

extern "C" void kernel_launch(void* const* d_in, const int* in_sizes, int n_in,
                              void* d_out, int out_size) {
    const float*  x    = (const float*)d_in[0];
    const float2* grid = (const float2*)d_in[1];
    float*        out  = (float*)d_out;

    static __half* scratch_ptr = nullptr;
    if (!scratch_ptr) cudaGetSymbolAddress((void**)&scratch_ptr, g_scratch);

    // 1) zero the fp16 scratch (standalone pure-write pass: cheapest form)
    cudaMemsetAsync(scratch_ptr, 0, (size_t)NOUT * sizeof(__half), 0);

    // 2) splat: 8 x 16B REDs per pixel, plane/slice-alternated issue order
    splat_kernel<<<NPIX / 256, 256>>>(x, grid);

    // 3) transpose split-plane scratch into f32 (B,C,H,W) output
    transpose_kernel<<<NPIX / 512, 128>>>((const __half2*)scratch_ptr, out);
}